// round 12
// baseline (speedup 1.0000x reference)
#include <cuda_runtime.h>
#include <cstdint>

#define T_DIM  1024
#define KSZ    64
#define NSZ    64
#define PCH    16                 // rows per pair-chunk
#define NCH    8                  // chunks per pair (8*16 = 128 rows/pair)
#define NBUF   4
#define STR    68                 // padded row stride (words): frag bank = 4g+tg, conflict-free
#define CHW    (PCH * STR)        // words per chunk buffer (1088)
#define PAIRW  (NBUF * CHW)       // words per pair region (4352)

__device__ __forceinline__ uint32_t f2tf32(float f) {
    uint32_t r; asm("cvt.rna.tf32.f32 %0, %1;" : "=r"(r) : "f"(f)); return r;
}
__device__ __forceinline__ uint32_t smem_u32(const void* p) {
    uint32_t a;
    asm("{ .reg .u64 t; cvta.to.shared.u64 t, %1; cvt.u32.u64 %0, t; }" : "=r"(a) : "l"(p));
    return a;
}
__device__ __forceinline__ void cp_async16(uint32_t dst, const void* src) {
    asm volatile("cp.async.cg.shared.global [%0], [%1], 16;" :: "r"(dst), "l"(src));
}

// one 16-row chunk (4 KB) loaded by the 64 threads of a warp pair; 4 cp.async/thread
__device__ __forceinline__ void issue_chunk(float* buf, const float* __restrict__ x,
                                            int t, int rowBase, int pid)
{
    #pragma unroll
    for (int i = 0; i < 4; i++) {
        int idx = pid + i * 64;            // float4 id 0..255
        int r   = idx >> 4;                // row 0..15
        int c4  = idx & 15;
        const float* src = x + ((size_t)(rowBase + r) * T_DIM + t) * KSZ + c4 * 4;
        cp_async16(smem_u32(&buf[r * STR + c4 * 4]), src);
    }
    asm volatile("cp.async.commit_group;");
}

__global__ __launch_bounds__(256, 2)
void parallel_linear_pairs(const float* __restrict__ x,
                           const float* __restrict__ W,
                           const float* __restrict__ bias,
                           float* __restrict__ out)
{
    extern __shared__ float smem[];
    float*    sAbase = smem;                                    // 4 pairs x PAIRW
    uint32_t* sW = reinterpret_cast<uint32_t*>(smem + 4 * PAIRW);
    float*    sB = reinterpret_cast<float*>(sW + NSZ * STR);

    const int t    = blockIdx.x;
    const int tid  = threadIdx.x;
    const int warp = tid >> 5;
    const int lane = tid & 31;
    const int g    = lane >> 2;         // 0..7
    const int tg   = lane & 3;          // 0..3
    const int pair  = warp >> 1;        // 0..3 : owns 128 batch rows
    const int nhalf = warp & 1;         // 32-col half
    const int pid   = tid & 63;         // thread id within pair

    float* pairBuf  = sAbase + pair * PAIRW;
    const int rowOrigin = pair * 128;
    const size_t rowstride = (size_t)T_DIM * KSZ;

    // ---- prologue: 3 chunks in flight per pair ----
    issue_chunk(pairBuf + 0 * CHW, x, t, rowOrigin + 0 * PCH, pid);
    issue_chunk(pairBuf + 1 * CHW, x, t, rowOrigin + 1 * PCH, pid);
    issue_chunk(pairBuf + 2 * CHW, x, t, rowOrigin + 2 * PCH, pid);

    // ---- stage W_t [64,64] -> tf32 bits (overlaps async X loads) ----
    {
        const float4* Wg = reinterpret_cast<const float4*>(W + (size_t)t * (NSZ * KSZ));
        #pragma unroll
        for (int i = 0; i < 4; i++) {
            int idx = tid + i * 256;
            int n   = idx >> 4;
            int c4  = idx & 15;
            float4 v = Wg[n * 16 + c4];
            uint4 u = make_uint4(f2tf32(v.x), f2tf32(v.y), f2tf32(v.z), f2tf32(v.w));
            *reinterpret_cast<uint4*>(&sW[n * STR + c4 * 4]) = u;
        }
    }
    if (tid < NSZ) sB[tid] = bias[t * NSZ + tid];
    __syncthreads();   // last CTA-wide barrier

    // ---- W fragments ONCE into registers: 4 n-tiles x 8 ks x 2 = 64 regs ----
    uint32_t wf0[4][8], wf1[4][8];
    #pragma unroll
    for (int nt = 0; nt < 4; nt++) {
        const int ncol = nhalf * 32 + nt * 8 + g;
        #pragma unroll
        for (int ks = 0; ks < 8; ks++) {
            wf0[nt][ks] = sW[ncol * STR + ks * 8 + tg];
            wf1[nt][ks] = sW[ncol * STR + ks * 8 + tg + 4];
        }
    }
    float bb0[4], bb1[4];
    #pragma unroll
    for (int nt = 0; nt < 4; nt++) {
        bb0[nt] = sB[nhalf * 32 + nt * 8 + 2 * tg];
        bb1[nt] = sB[nhalf * 32 + nt * 8 + 2 * tg + 1];
    }

    // ---- per-pair pipeline: 8 chunks, 4 private buffers, named-barrier sync ----
    #pragma unroll
    for (int c = 0; c < NCH; c++) {
        // chunk c resident when my pending groups <= min(2, NCH-1-c)
        if      (c <= NCH - 3) asm volatile("cp.async.wait_group 2;");
        else if (c == NCH - 2) asm volatile("cp.async.wait_group 1;");
        else                   asm volatile("cp.async.wait_group 0;");
        // pair-scope barrier: partner's half of chunk c visible; partner done with c-1
        asm volatile("bar.sync %0, 64;" :: "r"(pair + 1) : "memory");

        if (c + 3 < NCH)   // refill buffer of chunk c-1 with chunk c+3
            issue_chunk(pairBuf + ((c + 3) & (NBUF - 1)) * CHW, x, t,
                        rowOrigin + (c + 3) * PCH, pid);

        const float* aBuf = pairBuf + (c & (NBUF - 1)) * CHW;

        float acc[4][4];
        #pragma unroll
        for (int nt = 0; nt < 4; nt++)
            #pragma unroll
            for (int j = 0; j < 4; j++) acc[nt][j] = 0.f;

        #pragma unroll
        for (int ks = 0; ks < 8; ks++) {
            const int k0 = ks * 8;
            uint32_t a0 = f2tf32(aBuf[ g      * STR + k0 + tg]);
            uint32_t a1 = f2tf32(aBuf[(8 + g) * STR + k0 + tg]);
            uint32_t a2 = f2tf32(aBuf[ g      * STR + k0 + tg + 4]);
            uint32_t a3 = f2tf32(aBuf[(8 + g) * STR + k0 + tg + 4]);
            #pragma unroll
            for (int nt = 0; nt < 4; nt++) {
                asm volatile(
                    "mma.sync.aligned.m16n8k8.row.col.f32.tf32.tf32.f32 "
                    "{%0,%1,%2,%3}, {%4,%5,%6,%7}, {%8,%9}, {%0,%1,%2,%3};"
                    : "+f"(acc[nt][0]), "+f"(acc[nt][1]),
                      "+f"(acc[nt][2]), "+f"(acc[nt][3])
                    : "r"(a0), "r"(a1), "r"(a2), "r"(a3),
                      "r"(wf0[nt][ks]), "r"(wf1[nt][ks]));
            }
        }

        // epilogue: +bias, float2 stores
        const int grow = rowOrigin + c * PCH + g;
        #pragma unroll
        for (int nt = 0; nt < 4; nt++) {
            const int col = nhalf * 32 + nt * 8 + 2 * tg;
            size_t base = ((size_t)grow * T_DIM + t) * KSZ + col;
            *reinterpret_cast<float2*>(out + base) =
                make_float2(acc[nt][0] + bb0[nt], acc[nt][1] + bb1[nt]);
            *reinterpret_cast<float2*>(out + base + 8 * rowstride) =
                make_float2(acc[nt][2] + bb0[nt], acc[nt][3] + bb1[nt]);
        }
    }
}

extern "C" void kernel_launch(void* const* d_in, const int* in_sizes, int n_in,
                              void* d_out, int out_size)
{
    const float* x = (const float*)d_in[0];
    const float* W = (const float*)d_in[1];
    const float* b = (const float*)d_in[2];
    float* out     = (float*)d_out;

    const int smem_bytes =
        (4 * PAIRW + NSZ * STR + NSZ) * (int)sizeof(float);   // 87296 B

    cudaFuncSetAttribute(parallel_linear_pairs,
                         cudaFuncAttributeMaxDynamicSharedMemorySize, smem_bytes);

    parallel_linear_pairs<<<T_DIM, 256, smem_bytes>>>(x, W, b, out);
}